// round 5
// baseline (speedup 1.0000x reference)
#include <cuda_runtime.h>
#include <math.h>

#define NN      4096
#define IN_DIM  128
#define HEADS   4
#define OUT_DIM 64
#define HD      256   // HEADS*OUT_DIM
#define NB      512   // gather chunk size

// persistent scratch (allocation-free rule: __device__ globals)
__device__ float  g_h[NN * HD];      // 4 MB
__device__ float  g_si[NN * HEADS];
__device__ float  g_sj[NN * HEADS];
__device__ float  g_mx[HEADS];
__device__ float4 g_pk[NN * 4];      // per j: [0]=sj4 [1]=E4 [2]=F4 [3]=pad (64B/line)

// --------------------------------------------------------------------------
// Kernel 1: h = x @ W, with fused per-(node,head) score epilogue.
// --------------------------------------------------------------------------
__global__ __launch_bounds__(256) void gemm_h_kernel(const float* __restrict__ x,
                                                     const float* __restrict__ W,
                                                     const float* __restrict__ a_src,
                                                     const float* __restrict__ a_dst) {
    __shared__ float xs[16][IN_DIM];
    __shared__ float s_si[16][HEADS];
    __shared__ float s_sj[16][HEADS];
    const int t = threadIdx.x;
    const int row0 = blockIdx.x * 16;

    for (int idx = t; idx < 16 * IN_DIM; idx += 256)
        xs[idx >> 7][idx & 127] = x[row0 * IN_DIM + idx];
    if (t < 64) { s_si[t >> 2][t & 3] = 0.f; s_sj[t >> 2][t & 3] = 0.f; }
    __syncthreads();

    const int slot = t & 63;   // float4 column
    const int grp  = t >> 6;   // 4 row-groups of 4 rows
    float4 acc[4];
#pragma unroll
    for (int r = 0; r < 4; r++) acc[r] = make_float4(0.f, 0.f, 0.f, 0.f);

    const float4* W4 = (const float4*)W;
#pragma unroll 8
    for (int k = 0; k < IN_DIM; k++) {
        float4 wv = W4[k * 64 + slot];
#pragma unroll
        for (int r = 0; r < 4; r++) {
            float xv = xs[grp * 4 + r][k];
            acc[r].x = fmaf(xv, wv.x, acc[r].x);
            acc[r].y = fmaf(xv, wv.y, acc[r].y);
            acc[r].z = fmaf(xv, wv.z, acc[r].z);
            acc[r].w = fmaf(xv, wv.w, acc[r].w);
        }
    }
    float4* H4 = (float4*)g_h;
#pragma unroll
    for (int r = 0; r < 4; r++)
        H4[(size_t)(row0 + grp * 4 + r) * 64 + slot] = acc[r];

    // fused score epilogue: si = h.a_src, sj = h.a_dst
    const int d0 = (slot * 4) & 63;      // dim-within-head of component x
    const int hh = slot >> 4;            // head of this slot
    float as0 = a_src[d0], as1 = a_src[d0 + 1], as2 = a_src[d0 + 2], as3 = a_src[d0 + 3];
    float ad0 = a_dst[d0], ad1 = a_dst[d0 + 1], ad2 = a_dst[d0 + 2], ad3 = a_dst[d0 + 3];
#pragma unroll
    for (int r = 0; r < 4; r++) {
        float psi = acc[r].x * as0 + acc[r].y * as1 + acc[r].z * as2 + acc[r].w * as3;
        float psj = acc[r].x * ad0 + acc[r].y * ad1 + acc[r].z * ad2 + acc[r].w * ad3;
        atomicAdd(&s_si[grp * 4 + r][hh], psi);
        atomicAdd(&s_sj[grp * 4 + r][hh], psj);
    }
    __syncthreads();
    if (t < 64) {
        g_si[(row0 + (t >> 2)) * HEADS + (t & 3)] = s_si[t >> 2][t & 3];
        g_sj[(row0 + (t >> 2)) * HEADS + (t & 3)] = s_sj[t >> 2][t & 3];
    }
}

// --------------------------------------------------------------------------
// Kernel 2: g_mx[h] = max_n g_sj[n][h]. One block.
// --------------------------------------------------------------------------
__global__ __launch_bounds__(256) void max_sj_kernel() {
    __shared__ float red[HEADS][8];
    const int t = threadIdx.x, lane = t & 31, wid = t >> 5;
    float mx[HEADS];
#pragma unroll
    for (int h = 0; h < HEADS; h++) mx[h] = -INFINITY;
    const float4* s4 = (const float4*)g_sj;
    for (int i = t; i < NN; i += 256) {
        float4 v = s4[i];
        mx[0] = fmaxf(mx[0], v.x); mx[1] = fmaxf(mx[1], v.y);
        mx[2] = fmaxf(mx[2], v.z); mx[3] = fmaxf(mx[3], v.w);
    }
#pragma unroll
    for (int h = 0; h < HEADS; h++)
#pragma unroll
        for (int d = 16; d; d >>= 1)
            mx[h] = fmaxf(mx[h], __shfl_xor_sync(0xffffffffu, mx[h], d));
    if (lane == 0)
#pragma unroll
        for (int h = 0; h < HEADS; h++) red[h][wid] = mx[h];
    __syncthreads();
    if (t < HEADS) {
        float m = red[t][0];
#pragma unroll
        for (int w = 1; w < 8; w++) m = fmaxf(m, red[t][w]);
        g_mx[t] = m;
    }
}

// --------------------------------------------------------------------------
// Kernel 3: pack per-source factors: sj, E=exp(sj-mx), F=exp(0.2(sj-mx)).
// --------------------------------------------------------------------------
__global__ __launch_bounds__(256) void ef_kernel() {
    int j = blockIdx.x * 256 + threadIdx.x;
    if (j >= NN) return;
    float4 sj = ((const float4*)g_sj)[j];
    float m0 = g_mx[0], m1 = g_mx[1], m2 = g_mx[2], m3 = g_mx[3];
    float4 E = make_float4(__expf(sj.x - m0), __expf(sj.y - m1),
                           __expf(sj.z - m2), __expf(sj.w - m3));
    float4 F = make_float4(__expf(0.2f * (sj.x - m0)), __expf(0.2f * (sj.y - m1)),
                           __expf(0.2f * (sj.z - m2)), __expf(0.2f * (sj.w - m3)));
    g_pk[(j << 2) + 0] = sj;
    g_pk[(j << 2) + 1] = E;
    g_pk[(j << 2) + 2] = F;
}

// --------------------------------------------------------------------------
// Kernel 4: fused CSR-build + sparse gather attention. 1 block per dest row.
// p = exp(e - m) computed exactly via branch factorization: A*E | B*F.
// --------------------------------------------------------------------------
__global__ __launch_bounds__(256) void gather_kernel(const int* __restrict__ mask,
                                                     float* __restrict__ out) {
    __shared__ unsigned short nbr[NN];       // 8 KB
    __shared__ float p_sh[HEADS][NB];        // 8 KB
    __shared__ float4 acc_sh[4][64];         // 4 KB
    __shared__ float red_sh[HEADS][8];
    __shared__ int s_cnt;

    const int t    = threadIdx.x;
    const int lane = t & 31;
    const int wid  = t >> 5;
    const int row  = blockIdx.x;
    const int c    = t & 63;      // float4 column over 256 dims
    const int q    = t >> 6;      // j-subslot
    const int hc   = c >> 4;      // head owned in acc pass

    if (t == 0) s_cnt = 0;
    __syncthreads();

    // ---- build neighbor list from int32 mask row (order-free) ----
    const int4* m4 = (const int4*)mask + (size_t)row * (NN / 4);
#pragma unroll
    for (int g = 0; g < 4; g++) {
        int4 v = m4[g * 256 + t];
        int b0 = (v.x != 0), b1 = (v.y != 0), b2 = (v.z != 0), b3 = (v.w != 0);
        int mycnt = b0 + b1 + b2 + b3;
        int incl = mycnt;
#pragma unroll
        for (int d = 1; d < 32; d <<= 1) {
            int nn = __shfl_up_sync(0xffffffffu, incl, d);
            if (lane >= d) incl += nn;
        }
        int total = __shfl_sync(0xffffffffu, incl, 31);
        int off = incl - mycnt;
        int wbase = 0;
        if (lane == 0) wbase = atomicAdd(&s_cnt, total);
        wbase = __shfl_sync(0xffffffffu, wbase, 0);
        int jb = (g * 256 + t) * 4;
        int pos = wbase + off;
        if (b0) nbr[pos++] = (unsigned short)(jb);
        if (b1) nbr[pos++] = (unsigned short)(jb + 1);
        if (b2) nbr[pos++] = (unsigned short)(jb + 2);
        if (b3) nbr[pos++] = (unsigned short)(jb + 3);
    }
    __syncthreads();
    int cnt = s_cnt;
    if (cnt == 0) {             // degenerate row (prob ~0): deterministic fallback
        for (int jj = t; jj < NN; jj += 256) nbr[jj] = (unsigned short)jj;
        cnt = NN;
        __syncthreads();
    }

    // ---- per-row factors ----
    float si[HEADS], A[HEADS], B[HEADS];
#pragma unroll
    for (int h = 0; h < HEADS; h++) {
        si[h] = g_si[row * HEADS + h];
        float mxh = g_mx[h];
        float v = si[h] + mxh;
        float m = fmaxf(v, 0.2f * v);              // lrelu
        A[h] = __expf(v - m);                      // <= 1
        B[h] = __expf(0.2f * v - m);               // <= 1
    }
    float sum[HEADS] = {0.f, 0.f, 0.f, 0.f};
    float4 acc = make_float4(0.f, 0.f, 0.f, 0.f);

    const float4* gh4 = (const float4*)g_h;

    for (int base = 0; base < cnt; base += NB) {
        const int cn = min(NB, cnt - base);

        // ---- p-pass: zero-MUFU probability computation ----
        for (int jj = t; jj < cn; jj += 256) {
            int j = nbr[base + jj];
            const float4* pk = g_pk + ((size_t)j << 2);
            float4 sj = pk[0], E = pk[1], F = pk[2];
            float s0 = si[0] + sj.x, s1 = si[1] + sj.y;
            float s2 = si[2] + sj.z, s3 = si[3] + sj.w;
            float p0 = (s0 >= 0.f) ? A[0] * E.x : B[0] * F.x;
            float p1 = (s1 >= 0.f) ? A[1] * E.y : B[1] * F.y;
            float p2 = (s2 >= 0.f) ? A[2] * E.z : B[2] * F.z;
            float p3 = (s3 >= 0.f) ? A[3] * E.w : B[3] * F.w;
            p_sh[0][jj] = p0; p_sh[1][jj] = p1;
            p_sh[2][jj] = p2; p_sh[3][jj] = p3;
            sum[0] += p0; sum[1] += p1; sum[2] += p2; sum[3] += p3;
        }
        __syncthreads();

        // ---- acc-pass: acc += p_j * h[j] ----
#pragma unroll 8
        for (int jj = q; jj < cn; jj += 4) {
            int j = nbr[base + jj];
            float pv = p_sh[hc][jj];
            float4 hv = gh4[(size_t)j * 64 + c];
            acc.x = fmaf(pv, hv.x, acc.x);
            acc.y = fmaf(pv, hv.y, acc.y);
            acc.z = fmaf(pv, hv.z, acc.z);
            acc.w = fmaf(pv, hv.w, acc.w);
        }
        __syncthreads();
    }

    // ---- one-time reductions ----
#pragma unroll
    for (int h = 0; h < HEADS; h++)
#pragma unroll
        for (int d = 16; d; d >>= 1)
            sum[h] += __shfl_xor_sync(0xffffffffu, sum[h], d);
    if (lane == 0)
#pragma unroll
        for (int h = 0; h < HEADS; h++) red_sh[h][wid] = sum[h];
    acc_sh[q][c] = acc;
    __syncthreads();

    if (t < 64) {
        float4 s  = acc_sh[0][t];
        float4 a1 = acc_sh[1][t], a2 = acc_sh[2][t], a3 = acc_sh[3][t];
        s.x += a1.x + a2.x + a3.x;
        s.y += a1.y + a2.y + a3.y;
        s.z += a1.z + a2.z + a3.z;
        s.w += a1.w + a2.w + a3.w;
        int hh = t >> 4;
        float tot = 0.f;
#pragma unroll
        for (int w = 0; w < 8; w++) tot += red_sh[hh][w];
        float inv = 1.0f / tot;
        s.x *= inv; s.y *= inv; s.z *= inv; s.w *= inv;
        ((float4*)out)[(size_t)row * 64 + t] = s;
    }
}

// --------------------------------------------------------------------------
extern "C" void kernel_launch(void* const* d_in, const int* in_sizes, int n_in,
                              void* d_out, int out_size) {
    const float* x     = (const float*)d_in[0];
    const int*   mask  = (const int*)d_in[1];
    const float* W     = (const float*)d_in[2];
    const float* a_src = (const float*)d_in[3];
    const float* a_dst = (const float*)d_in[4];
    float*       out   = (float*)d_out;

    gemm_h_kernel<<<NN / 16, 256>>>(x, W, a_src, a_dst);
    max_sj_kernel<<<1, 256>>>();
    ef_kernel<<<NN / 256, 256>>>();
    gather_kernel<<<NN, 256>>>(mask, out);
}

// round 6
// speedup vs baseline: 1.5576x; 1.5576x over previous
#include <cuda_runtime.h>
#include <cuda_fp16.h>
#include <math.h>

#define NN      4096
#define IN_DIM  128
#define HEADS   4
#define OUT_DIM 64
#define HD      256   // HEADS*OUT_DIM
#define NB      512   // gather chunk size
#define NBP     (NB + 8)

// persistent scratch (allocation-free rule: __device__ globals)
__device__ uint4          g_hb[NN * 32];           // h in fp16: 4096 x 256 x 2B = 2 MB
__device__ float          g_si[NN * HEADS];
__device__ float          g_sj[NN * HEADS];
__device__ float          g_mx[HEADS];
__device__ unsigned short g_nbr[(size_t)NN * NN];  // padded CSR
__device__ int            g_cnt[NN];

// --------------------------------------------------------------------------
// Fat kernel: blocks [0,256) = gemm h=x@W + fused scores (fp16 h out)
//             blocks [256,768) = CSR build from int32 adjacency
// --------------------------------------------------------------------------
__global__ __launch_bounds__(256) void fat_kernel(const float* __restrict__ x,
                                                  const float* __restrict__ W,
                                                  const float* __restrict__ a_src,
                                                  const float* __restrict__ a_dst,
                                                  const int* __restrict__ mask) {
    __shared__ float xs[16][IN_DIM];
    __shared__ float s_si[16][HEADS];
    __shared__ float s_sj[16][HEADS];
    const int t = threadIdx.x;

    if (blockIdx.x < 256) {
        // ================= GEMM part =================
        const int row0 = blockIdx.x * 16;
        for (int idx = t; idx < 16 * IN_DIM; idx += 256)
            xs[idx >> 7][idx & 127] = x[row0 * IN_DIM + idx];
        if (t < 64) { s_si[t >> 2][t & 3] = 0.f; s_sj[t >> 2][t & 3] = 0.f; }
        __syncthreads();

        const int slot = t & 63;   // float4 column (dims slot*4..slot*4+3)
        const int grp  = t >> 6;   // 4 row-groups of 4 rows
        float4 acc[4];
#pragma unroll
        for (int r = 0; r < 4; r++) acc[r] = make_float4(0.f, 0.f, 0.f, 0.f);

        const float4* W4 = (const float4*)W;
#pragma unroll 8
        for (int k = 0; k < IN_DIM; k++) {
            float4 wv = W4[k * 64 + slot];
#pragma unroll
            for (int r = 0; r < 4; r++) {
                float xv = xs[grp * 4 + r][k];
                acc[r].x = fmaf(xv, wv.x, acc[r].x);
                acc[r].y = fmaf(xv, wv.y, acc[r].y);
                acc[r].z = fmaf(xv, wv.z, acc[r].z);
                acc[r].w = fmaf(xv, wv.w, acc[r].w);
            }
        }
        // fp16 h store
        __half2* HB = (__half2*)g_hb;
#pragma unroll
        for (int r = 0; r < 4; r++) {
            int row = row0 + grp * 4 + r;
            HB[(size_t)row * 128 + slot * 2]     = __floats2half2_rn(acc[r].x, acc[r].y);
            HB[(size_t)row * 128 + slot * 2 + 1] = __floats2half2_rn(acc[r].z, acc[r].w);
        }
        // fused score epilogue
        const int d0 = (slot * 4) & 63;
        const int hh = slot >> 4;
        float as0 = a_src[d0], as1 = a_src[d0 + 1], as2 = a_src[d0 + 2], as3 = a_src[d0 + 3];
        float ad0 = a_dst[d0], ad1 = a_dst[d0 + 1], ad2 = a_dst[d0 + 2], ad3 = a_dst[d0 + 3];
#pragma unroll
        for (int r = 0; r < 4; r++) {
            float psi = acc[r].x * as0 + acc[r].y * as1 + acc[r].z * as2 + acc[r].w * as3;
            float psj = acc[r].x * ad0 + acc[r].y * ad1 + acc[r].z * ad2 + acc[r].w * ad3;
            atomicAdd(&s_si[grp * 4 + r][hh], psi);
            atomicAdd(&s_sj[grp * 4 + r][hh], psj);
        }
        __syncthreads();
        if (t < 64) {
            g_si[(row0 + (t >> 2)) * HEADS + (t & 3)] = s_si[t >> 2][t & 3];
            g_sj[(row0 + (t >> 2)) * HEADS + (t & 3)] = s_sj[t >> 2][t & 3];
        }
    } else {
        // ================= CSR part =================
        const int warp = t >> 5, lane = t & 31;
        const int row  = (blockIdx.x - 256) * 8 + warp;
        const int4* m4 = (const int4*)mask + (size_t)row * (NN / 4);
        unsigned short* dst = g_nbr + (size_t)row * NN;

        int base = 0;
#pragma unroll 4
        for (int it = 0; it < NN / 128; it++) {
            int4 v = m4[it * 32 + lane];
            int b0 = (v.x != 0), b1 = (v.y != 0), b2 = (v.z != 0), b3 = (v.w != 0);
            int mycnt = b0 + b1 + b2 + b3;
            int incl = mycnt;
#pragma unroll
            for (int d = 1; d < 32; d <<= 1) {
                int nn = __shfl_up_sync(0xffffffffu, incl, d);
                if (lane >= d) incl += nn;
            }
            int total = __shfl_sync(0xffffffffu, incl, 31);
            int off = incl - mycnt;
            int jb  = (it * 32 + lane) * 4;
            int pos = base + off;
            if (b0) dst[pos++] = (unsigned short)(jb);
            if (b1) dst[pos++] = (unsigned short)(jb + 1);
            if (b2) dst[pos++] = (unsigned short)(jb + 2);
            if (b3) dst[pos++] = (unsigned short)(jb + 3);
            base += total;
        }
        if (lane == 0) g_cnt[row] = base;
    }
}

// --------------------------------------------------------------------------
// Kernel 2: g_mx[h] = max_n g_sj[n][h]. One block.
// --------------------------------------------------------------------------
__global__ __launch_bounds__(256) void max_sj_kernel() {
    __shared__ float red[HEADS][8];
    const int t = threadIdx.x, lane = t & 31, wid = t >> 5;
    float mx[HEADS];
#pragma unroll
    for (int h = 0; h < HEADS; h++) mx[h] = -INFINITY;
    const float4* s4 = (const float4*)g_sj;
    for (int i = t; i < NN; i += 256) {
        float4 v = s4[i];
        mx[0] = fmaxf(mx[0], v.x); mx[1] = fmaxf(mx[1], v.y);
        mx[2] = fmaxf(mx[2], v.z); mx[3] = fmaxf(mx[3], v.w);
    }
#pragma unroll
    for (int h = 0; h < HEADS; h++)
#pragma unroll
        for (int d = 16; d; d >>= 1)
            mx[h] = fmaxf(mx[h], __shfl_xor_sync(0xffffffffu, mx[h], d));
    if (lane == 0)
#pragma unroll
        for (int h = 0; h < HEADS; h++) red[h][wid] = mx[h];
    __syncthreads();
    if (t < HEADS) {
        float m = red[t][0];
#pragma unroll
        for (int w = 1; w < 8; w++) m = fmaxf(m, red[t][w]);
        g_mx[t] = m;
    }
}

// --------------------------------------------------------------------------
// Kernel 3: sparse gather attention. 1 block per dest row, single-pass
// softmax (m from global sj max), fp16 h aggregation.
// thread map acc-pass: c = t&31 (8-dim slot), q = t>>5 (j-subslot), hc = c>>3.
// --------------------------------------------------------------------------
__global__ __launch_bounds__(256) void gather_kernel(float* __restrict__ out) {
    __shared__ unsigned short nbr[NN];          // 8 KB
    __shared__ float p_sh[HEADS][NBP];          // ~8.1 KB (padded vs bank conflict)
    __shared__ float acc_sh[8][32][8];          // 8 KB
    __shared__ float red_sh[HEADS][8];
    __shared__ float tot_sh[HEADS];

    const int t    = threadIdx.x;
    const int lane = t & 31;
    const int wid  = t >> 5;
    const int row  = blockIdx.x;
    const int c    = t & 31;
    const int q    = t >> 5;
    const int hc   = c >> 3;

    // ---- stage full neighbor list ----
    int cnt = g_cnt[row];
    const bool uniform = (cnt == 0);
    if (uniform) cnt = NN;
    const unsigned short* nrow = g_nbr + (size_t)row * NN;
    for (int jj = t; jj < cnt; jj += 256)
        nbr[jj] = uniform ? (unsigned short)jj : nrow[jj];

    // ---- per-row factors ----
    float si[HEADS], m[HEADS];
#pragma unroll
    for (int h = 0; h < HEADS; h++) {
        si[h] = g_si[row * HEADS + h];
        float v = si[h] + g_mx[h];
        m[h] = fmaxf(v, 0.2f * v);        // lrelu, >= all row scores
    }
    float sum[HEADS] = {0.f, 0.f, 0.f, 0.f};
    float acc[8] = {0.f, 0.f, 0.f, 0.f, 0.f, 0.f, 0.f, 0.f};

    const float4* gsj4 = (const float4*)g_sj;
    __syncthreads();

    for (int base = 0; base < cnt; base += NB) {
        const int cn = min(NB, cnt - base);

        // ---- p-pass ----
        for (int jj = t; jj < cn; jj += 256) {
            float4 sj = gsj4[nbr[base + jj]];
            float e0 = si[0] + sj.x; e0 = fmaxf(e0, 0.2f * e0);
            float e1 = si[1] + sj.y; e1 = fmaxf(e1, 0.2f * e1);
            float e2 = si[2] + sj.z; e2 = fmaxf(e2, 0.2f * e2);
            float e3 = si[3] + sj.w; e3 = fmaxf(e3, 0.2f * e3);
            float p0 = uniform ? 1.f : __expf(e0 - m[0]);
            float p1 = uniform ? 1.f : __expf(e1 - m[1]);
            float p2 = uniform ? 1.f : __expf(e2 - m[2]);
            float p3 = uniform ? 1.f : __expf(e3 - m[3]);
            p_sh[0][jj] = p0; p_sh[1][jj] = p1;
            p_sh[2][jj] = p2; p_sh[3][jj] = p3;
            sum[0] += p0; sum[1] += p1; sum[2] += p2; sum[3] += p3;
        }
        __syncthreads();

        // ---- acc-pass: fp16 h rows, 16B (8 dims) per thread per edge ----
#pragma unroll 4
        for (int jj = q; jj < cn; jj += 8) {
            int j = nbr[base + jj];
            float pv = p_sh[hc][jj];
            uint4 hv = g_hb[(size_t)j * 32 + c];
            float2 f0 = __half22float2(*(__half2*)&hv.x);
            float2 f1 = __half22float2(*(__half2*)&hv.y);
            float2 f2 = __half22float2(*(__half2*)&hv.z);
            float2 f3 = __half22float2(*(__half2*)&hv.w);
            acc[0] = fmaf(pv, f0.x, acc[0]);
            acc[1] = fmaf(pv, f0.y, acc[1]);
            acc[2] = fmaf(pv, f1.x, acc[2]);
            acc[3] = fmaf(pv, f1.y, acc[3]);
            acc[4] = fmaf(pv, f2.x, acc[4]);
            acc[5] = fmaf(pv, f2.y, acc[5]);
            acc[6] = fmaf(pv, f3.x, acc[6]);
            acc[7] = fmaf(pv, f3.y, acc[7]);
        }
        __syncthreads();
    }

    // ---- reductions ----
#pragma unroll
    for (int h = 0; h < HEADS; h++)
#pragma unroll
        for (int d = 16; d; d >>= 1)
            sum[h] += __shfl_xor_sync(0xffffffffu, sum[h], d);
    if (lane == 0)
#pragma unroll
        for (int h = 0; h < HEADS; h++) red_sh[h][wid] = sum[h];
#pragma unroll
    for (int d = 0; d < 8; d++) acc_sh[q][c][d] = acc[d];
    __syncthreads();
    if (t < HEADS) {
        float tt = 0.f;
#pragma unroll
        for (int w = 0; w < 8; w++) tt += red_sh[t][w];
        tot_sh[t] = tt;
    }
    __syncthreads();

    // thread t owns output dim t (0..255)
    float s = 0.f;
#pragma unroll
    for (int qq = 0; qq < 8; qq++) s += acc_sh[qq][t >> 3][t & 7];
    s *= (1.0f / tot_sh[t >> 6]);
    out[(size_t)row * HD + t] = s;
}

// --------------------------------------------------------------------------
extern "C" void kernel_launch(void* const* d_in, const int* in_sizes, int n_in,
                              void* d_out, int out_size) {
    const float* x     = (const float*)d_in[0];
    const int*   mask  = (const int*)d_in[1];
    const float* W     = (const float*)d_in[2];
    const float* a_src = (const float*)d_in[3];
    const float* a_dst = (const float*)d_in[4];
    float*       out   = (float*)d_out;

    fat_kernel<<<768, 256>>>(x, W, a_src, a_dst, mask);
    max_sj_kernel<<<1, 256>>>();
    gather_kernel<<<NN, 256>>>(out);
}